// round 13
// baseline (speedup 1.0000x reference)
#include <cuda_runtime.h>
#include <cuda_fp16.h>
#include <stdint.h>

// ---------------- problem constants ----------------
#define BATCH  2
#define TQ     2048
#define CDIM   1024
#define NHEAD  16
#define DHEAD  64
#define C3     (3 * CDIM)
#define NQT2   (TQ / 128)
#define NROWS  (BATCH * NHEAD * TQ)
#define QKVN   (BATCH * NHEAD * TQ * DHEAD)
#define LN2F   0.6931471805599453f
#define SC2F   0.1803368801111601f   // 0.125 * log2(e)

#define NQKV_B  768   // 32 bm x 24 bn
#define NFLASH_B 512
#define NPROJ_B 256   // 32 bm x 8 bn

// ---------------- fp16 planes + flags (device scratch) ----------------
__device__ __align__(16) __half gX[BATCH*TQ*CDIM];
__device__ __align__(16) __half gWA[CDIM*C3];
__device__ __align__(16) __half gWP[CDIM*CDIM];
__device__ __align__(16) __half gQ[QKVN];   // stored PRE-SCALED by SC2F
__device__ __align__(16) __half gK[QKVN];
__device__ __align__(16) __half gV[QKVN];
__device__ __align__(16) __half gY[BATCH*TQ*CDIM];
__device__ float g_ent[BATCH * NHEAD * NQT2];
__device__ int g_fq[32];   // per token-row-tile: # of 24 qkv column tiles done
__device__ int g_ff[32];   // per token-row-tile: # of 16 flash head-blocks done

// ---------------- helpers ----------------
__device__ __forceinline__ unsigned round2h(float a, float b) {
    __half2 h = __floats2half2_rn(a, b);
    return *reinterpret_cast<unsigned*>(&h);
}
__device__ __forceinline__ float ex2f(float x) {
    float r; asm("ex2.approx.f32 %0, %1;" : "=f"(r) : "f"(x)); return r;
}
__device__ __forceinline__ unsigned ex2h2(unsigned x) {
    unsigned r; asm("ex2.approx.f16x2 %0, %1;" : "=r"(r) : "r"(x)); return r;
}
__device__ __forceinline__ void mma16(float* c, const unsigned* a, unsigned b0, unsigned b1) {
    asm("mma.sync.aligned.m16n8k16.row.col.f32.f16.f16.f32 "
        "{%0,%1,%2,%3},{%4,%5,%6,%7},{%8,%9},{%0,%1,%2,%3};"
        : "+f"(c[0]), "+f"(c[1]), "+f"(c[2]), "+f"(c[3])
        : "r"(a[0]), "r"(a[1]), "r"(a[2]), "r"(a[3]), "r"(b0), "r"(b1));
}
__device__ __forceinline__ void ldsm4(unsigned& r0, unsigned& r1, unsigned& r2, unsigned& r3, uint32_t a) {
    asm volatile("ldmatrix.sync.aligned.m8n8.x4.shared.b16 {%0,%1,%2,%3},[%4];"
        : "=r"(r0), "=r"(r1), "=r"(r2), "=r"(r3) : "r"(a));
}
__device__ __forceinline__ void ldsm4t(unsigned& r0, unsigned& r1, unsigned& r2, unsigned& r3, uint32_t a) {
    asm volatile("ldmatrix.sync.aligned.m8n8.x4.trans.shared.b16 {%0,%1,%2,%3},[%4];"
        : "=r"(r0), "=r"(r1), "=r"(r2), "=r"(r3) : "r"(a));
}
__device__ __forceinline__ void cpa16(uint32_t d, const void* s) {
    asm volatile("cp.async.ca.shared.global [%0],[%1],16;" :: "r"(d), "l"(s));
}
#define CP_COMMIT() asm volatile("cp.async.commit_group;" ::: "memory")
#define CP_WAIT(N)  asm volatile("cp.async.wait_group %0;" :: "n"(N) : "memory")

// =====================================================================
// prep: round inputs to fp16 planes + zero flags
// =====================================================================
#define NX4 (BATCH * TQ * CDIM / 4)
#define NA4 (CDIM * C3 / 4)
#define NP4 (CDIM * CDIM / 4)
#define NT4 (NX4 + NA4 + NP4)
__global__ void prep_kernel(const float* __restrict__ x,
                            const float* __restrict__ wa,
                            const float* __restrict__ wp)
{
    if (blockIdx.x == 0 && threadIdx.x < 64) {
        if (threadIdx.x < 32) g_fq[threadIdx.x] = 0;
        else                  g_ff[threadIdx.x - 32] = 0;
    }
    int base = blockIdx.x * (blockDim.x * 4) + threadIdx.x;
#pragma unroll
    for (int u = 0; u < 4; u++) {
        int i = base + u * 256;
        if (i >= NT4) return;
        const float* in; __half* out; int j;
        if (i < NX4)            { in = x;  out = gX;  j = i; }
        else if (i < NX4 + NA4) { in = wa; out = gWA; j = i - NX4; }
        else                    { in = wp; out = gWP; j = i - NX4 - NA4; }
        float4 v = ((const float4*)in)[j];
        ((uint2*)out)[j] = make_uint2(round2h(v.x, v.y), round2h(v.z, v.w));
    }
}

// =====================================================================
// shared-memory layouts
// =====================================================================
#define GSTG 16384
#define FKV0 16384
#define FSTG 16384
extern __shared__ char dsm[];

// ---------------------------------------------------------------------
// GEMM tile body (128x128, BK=32, 3-stage cp.async).
// MODE 0: fp32 C. MODE 1: qkv scatter (Q pre-scaled).
// ---------------------------------------------------------------------
__device__ __forceinline__ void gemm_issue(
    uint32_t s0, const __half* A, const __half* B,
    int bm, int bn, int k0, int K, int N, int tid)
{
#pragma unroll
    for (int it = 0; it < 2; it++) {
        int id = tid + it * 256;
        int r = id >> 2, c = id & 3;
        uint32_t d = s0 + r * 64 + ((c ^ ((r >> 1) & 3)) << 4);
        cpa16(d, A + (size_t)(bm + r) * K + k0 + c * 8);
    }
#pragma unroll
    for (int it = 0; it < 2; it++) {
        int id = tid + it * 256;
        int k = id >> 4, c = id & 15;
        uint32_t d = s0 + 8192 + k * 256 + ((c ^ (k & 7)) << 4);
        cpa16(d, B + (size_t)(k0 + k) * N + bn + c * 8);
    }
}

template<int MODE>
__device__ void gemm_tile(const __half* __restrict__ A,
                          const __half* __restrict__ B,
                          float* __restrict__ C,
                          int N, int K, int bm, int bn)
{
    const uint32_t sb = (uint32_t)__cvta_generic_to_shared(dsm);
    const int tid = threadIdx.x, lane = tid & 31, wid = tid >> 5;
    const int g = lane >> 2, t = lane & 3;
    const int m8 = lane >> 3, ri = lane & 7;
    const int wm = wid & 3, wn = wid >> 2;

    float acc[2][8][4];
#pragma unroll
    for (int mt = 0; mt < 2; mt++)
#pragma unroll
        for (int nt = 0; nt < 8; nt++)
#pragma unroll
            for (int i = 0; i < 4; i++) acc[mt][nt][i] = 0.f;

    const int NCH = K / 32;
    gemm_issue(sb,        A, B, bm, bn, 0,  K, N, tid); CP_COMMIT();
    gemm_issue(sb + GSTG, A, B, bm, bn, 32, K, N, tid); CP_COMMIT();

    for (int ch = 0; ch < NCH; ch++) {
        if (ch + 2 < NCH)
            gemm_issue(sb + ((ch + 2) % 3) * GSTG, A, B,
                       bm, bn, (ch + 2) * 32, K, N, tid);
        CP_COMMIT();
        CP_WAIT(2);
        __syncthreads();

        const uint32_t s0 = sb + (ch % 3) * GSTG;
#pragma unroll
        for (int ks = 0; ks < 2; ks++) {
            unsigned ah[2][4];
#pragma unroll
            for (int mt = 0; mt < 2; mt++) {
                int row = wm * 32 + mt * 16 + (m8 & 1) * 8 + ri;
                int c4  = 2 * ks + (m8 >> 1);
                uint32_t a = s0 + row * 64 + ((c4 ^ ((row >> 1) & 3)) << 4);
                ldsm4(ah[mt][0], ah[mt][1], ah[mt][2], ah[mt][3], a);
            }
#pragma unroll
            for (int ntp = 0; ntp < 4; ntp++) {
                int kr = 16 * ks + (m8 & 1) * 8 + ri;
                int cc = wn * 8 + ntp * 2 + (m8 >> 1);
                uint32_t ba = s0 + 8192 + kr * 256 + ((cc ^ (kr & 7)) << 4);
                unsigned bh[4];
                ldsm4t(bh[0], bh[1], bh[2], bh[3], ba);
                mma16(acc[0][ntp * 2 + 0], ah[0], bh[0], bh[1]);
                mma16(acc[1][ntp * 2 + 0], ah[1], bh[0], bh[1]);
                mma16(acc[0][ntp * 2 + 1], ah[0], bh[2], bh[3]);
                mma16(acc[1][ntp * 2 + 1], ah[1], bh[2], bh[3]);
            }
        }
        __syncthreads();
    }

    if (MODE == 0) {
#pragma unroll
        for (int mt = 0; mt < 2; mt++) {
#pragma unroll
            for (int nt = 0; nt < 8; nt++) {
                const int row = bm + wm * 32 + mt * 16 + g;
                const int col = bn + wn * 64 + nt * 8 + 2 * t;
                *(float2*)&C[(size_t)row * N + col] =
                    make_float2(acc[mt][nt][0], acc[mt][nt][1]);
                *(float2*)&C[(size_t)(row + 8) * N + col] =
                    make_float2(acc[mt][nt][2], acc[mt][nt][3]);
            }
        }
    } else {
#pragma unroll
        for (int mt = 0; mt < 2; mt++) {
#pragma unroll
            for (int nt = 0; nt < 8; nt++) {
                const int row = bm + wm * 32 + mt * 16 + g;
                const int col = bn + wn * 64 + nt * 8 + 2 * t;
                const int sec = col >> 10, hh = (col >> 6) & 15, d = col & 63;
                const int bb = row >> 11, tok = row & 2047;
                size_t idx = (((size_t)bb * NHEAD + hh) * TQ + tok) * DHEAD + d;
                __half* p = (sec == 0) ? gQ : ((sec == 1) ? gK : gV);
                const float sc = (sec == 0) ? SC2F : 1.f;
                *(unsigned*)&p[idx] =
                    round2h(acc[mt][nt][0] * sc, acc[mt][nt][1] * sc);
                *(unsigned*)&p[idx + 8 * DHEAD] =
                    round2h(acc[mt][nt][2] * sc, acc[mt][nt][3] * sc);
            }
        }
    }
}

// ---------------------------------------------------------------------
// flash role body
// ---------------------------------------------------------------------
__device__ __forceinline__ void flash_issue_kv(uint32_t s0, size_t base, int j, int tid)
{
#pragma unroll
    for (int it = 0; it < 2; it++) {
        int id = tid + it * 256;
        int r = id >> 3, c = id & 7;
        uint32_t d = s0 + r * 128 + ((c ^ (r & 7)) << 4);
        size_t go = base + (size_t)(j * 64 + r) * DHEAD + c * 8;
        cpa16(d,        gK + go);
        cpa16(d + 8192, gV + go);
    }
}

__device__ void flash_role(int fid)
{
    __shared__ float sred[64];
    const uint32_t sb = (uint32_t)__cvta_generic_to_shared(dsm);
    const int qt = fid >> 5;                  // ASCENDING: overlap with producer
    const int hb = fid & 31;
    const int h = hb & 15, b = hb >> 4;
    const int tid = threadIdx.x, lane = tid & 31, wid = tid >> 5;
    const int g = lane >> 2, t = lane & 3;
    const int m8 = lane >> 3, ri = lane & 7;
    const size_t base = (size_t)(b * NHEAD + h) * TQ * DHEAD;
    const int nj = 2 * qt + 2;

    // ---- acquire: wait for QKV row tiles b*16 .. b*16+qt ----
    if (tid == 0) {
        for (int i = 0; i <= qt; i++)
            while (atomicAdd(&g_fq[b * 16 + i], 0) < 24) {}
        __threadfence();
    }
    __syncthreads();

    // ---- prologue: Q + KV0 (group A), KV1 (group B) ----
#pragma unroll
    for (int it = 0; it < 4; it++) {
        int id = tid + it * 256;
        int r = id >> 3, c = id & 7;
        uint32_t d = sb + r * 128 + ((c ^ (r & 7)) << 4);
        cpa16(d, gQ + base + (size_t)(qt * 128 + r) * DHEAD + c * 8);
    }
    flash_issue_kv(sb + FKV0, base, 0, tid);
    CP_COMMIT();
    flash_issue_kv(sb + FKV0 + FSTG, base, 1, tid);
    CP_COMMIT();
    CP_WAIT(1);
    __syncthreads();

    unsigned qh[4][4];
#pragma unroll
    for (int ks = 0; ks < 4; ks++) {
        int row = wid * 16 + (m8 & 1) * 8 + ri;
        int c = 2 * ks + (m8 >> 1);
        uint32_t a = sb + row * 128 + ((c ^ (row & 7)) << 4);
        ldsm4(qh[ks][0], qh[ks][1], qh[ks][2], qh[ks][3], a);
    }

    float oc[8][4];
#pragma unroll
    for (int nt = 0; nt < 8; nt++)
#pragma unroll
        for (int i = 0; i < 4; i++) oc[nt][i] = 0.f;

    float m0 = -1e30f, m1 = -1e30f, l0s = 0.f, l1s = 0.f, aa0 = 0.f, aa1 = 0.f;
    const int rowbase = qt * 128 + wid * 16;
    int st2 = 2;

    for (int j = 0; j < nj; j++) {
        CP_WAIT(1);
        __syncthreads();
        if (j + 2 < nj) flash_issue_kv(sb + FKV0 + st2 * FSTG, base, j + 2, tid);
        CP_COMMIT();
        const uint32_t kv = sb + FKV0 + (st2 == 2 ? 0 : st2 + 1) * FSTG;
        st2 = (st2 == 2) ? 0 : st2 + 1;

        const bool active = (rowbase + 16) > (j * 64);
        if (!active) continue;

        float sc[8][4];
#pragma unroll
        for (int nt = 0; nt < 8; nt++)
#pragma unroll
            for (int i = 0; i < 4; i++) sc[nt][i] = 0.f;

#pragma unroll
        for (int ks = 0; ks < 4; ks++) {
#pragma unroll
            for (int ntp = 0; ntp < 4; ntp++) {
                int kr = ntp * 16 + (m8 & 1) * 8 + ri;
                int c = 2 * ks + (m8 >> 1);
                uint32_t ka = kv + kr * 128 + ((c ^ (kr & 7)) << 4);
                unsigned kh[4];
                ldsm4(kh[0], kh[1], kh[2], kh[3], ka);
                mma16(sc[2 * ntp],     qh[ks], kh[0], kh[2]);
                mma16(sc[2 * ntp + 1], qh[ks], kh[1], kh[3]);
            }
        }

        if ((j * 64 + 63) > rowbase) {
#pragma unroll
            for (int nt = 0; nt < 8; nt++) {
#pragma unroll
                for (int cc = 0; cc < 4; cc++) {
                    int col = j * 64 + nt * 8 + 2 * t + (cc & 1);
                    int row = rowbase + g + ((cc >> 1) << 3);
                    if (col > row) sc[nt][cc] = -1e30f;
                }
            }
        }

        float mt0 = -1e30f, mt1 = -1e30f;
#pragma unroll
        for (int nt = 0; nt < 8; nt++) {
            mt0 = fmaxf(mt0, fmaxf(sc[nt][0], sc[nt][1]));
            mt1 = fmaxf(mt1, fmaxf(sc[nt][2], sc[nt][3]));
        }
        mt0 = fmaxf(mt0, __shfl_xor_sync(0xffffffffu, mt0, 1));
        mt0 = fmaxf(mt0, __shfl_xor_sync(0xffffffffu, mt0, 2));
        mt1 = fmaxf(mt1, __shfl_xor_sync(0xffffffffu, mt1, 1));
        mt1 = fmaxf(mt1, __shfl_xor_sync(0xffffffffu, mt1, 2));

        const float mn0 = fmaxf(m0, mt0), mn1 = fmaxf(m1, mt1);
        const float ex0 = ex2f(m0 - mn0), ex1 = ex2f(m1 - mn1);
        const __half2 mn0h = __float2half2_rn(mn0);
        const __half2 mn1h = __float2half2_rn(mn1);

        unsigned ph0[8], ph1[8];
        float ls0 = 0.f, ls1 = 0.f, as0 = 0.f, as1 = 0.f;
#pragma unroll
        for (int nt = 0; nt < 8; nt++) {
            __half2 h0 = __floats2half2_rn(sc[nt][0], sc[nt][1]);
            __half2 h1 = __floats2half2_rn(sc[nt][2], sc[nt][3]);
            __half2 d0 = __hsub2(h0, mn0h);
            __half2 d1 = __hsub2(h1, mn1h);
            unsigned p0 = ex2h2(*reinterpret_cast<unsigned*>(&d0));
            unsigned p1 = ex2h2(*reinterpret_cast<unsigned*>(&d1));
            ph0[nt] = p0; ph1[nt] = p1;
            float2 f0 = __half22float2(*reinterpret_cast<__half2*>(&p0));
            float2 f1 = __half22float2(*reinterpret_cast<__half2*>(&p1));
            ls0 += f0.x + f0.y;  ls1 += f1.x + f1.y;
            as0 += f0.x * sc[nt][0] + f0.y * sc[nt][1];
            as1 += f1.x * sc[nt][2] + f1.y * sc[nt][3];
        }
        ls0 += __shfl_xor_sync(0xffffffffu, ls0, 1);
        ls0 += __shfl_xor_sync(0xffffffffu, ls0, 2);
        ls1 += __shfl_xor_sync(0xffffffffu, ls1, 1);
        ls1 += __shfl_xor_sync(0xffffffffu, ls1, 2);
        as0 += __shfl_xor_sync(0xffffffffu, as0, 1);
        as0 += __shfl_xor_sync(0xffffffffu, as0, 2);
        as1 += __shfl_xor_sync(0xffffffffu, as1, 1);
        as1 += __shfl_xor_sync(0xffffffffu, as1, 2);

        l0s = l0s * ex0 + ls0;  aa0 = aa0 * ex0 + as0;  m0 = mn0;
        l1s = l1s * ex1 + ls1;  aa1 = aa1 * ex1 + as1;  m1 = mn1;

#pragma unroll
        for (int nt = 0; nt < 8; nt++) {
            oc[nt][0] *= ex0; oc[nt][1] *= ex0;
            oc[nt][2] *= ex1; oc[nt][3] *= ex1;
        }

#pragma unroll
        for (int ks = 0; ks < 4; ks++) {
            unsigned aH[4] = {ph0[2*ks], ph1[2*ks], ph0[2*ks+1], ph1[2*ks+1]};
#pragma unroll
            for (int ntp = 0; ntp < 4; ntp++) {
                int vr = 16 * ks + (m8 & 1) * 8 + ri;
                int c = ntp * 2 + (m8 >> 1);
                uint32_t va = kv + 8192 + vr * 128 + ((c ^ (vr & 7)) << 4);
                unsigned vh[4];
                ldsm4t(vh[0], vh[1], vh[2], vh[3], va);
                mma16(oc[2 * ntp],     aH, vh[0], vh[1]);
                mma16(oc[2 * ntp + 1], aH, vh[2], vh[3]);
            }
        }
    }

    // ---- epilogue: write yatt fp16 ----
    const float inv0 = 1.f / l0s, inv1 = 1.f / l1s;
    const int trow = rowbase + g;
#pragma unroll
    for (int nt = 0; nt < 8; nt++) {
        const int col = h * DHEAD + nt * 8 + 2 * t;
        size_t idx = ((size_t)b * TQ + trow) * CDIM + col;
        *(unsigned*)&gY[idx] = round2h(oc[nt][0] * inv0, oc[nt][1] * inv0);
        *(unsigned*)&gY[idx + 8 * CDIM] = round2h(oc[nt][2] * inv1, oc[nt][3] * inv1);
    }
    __threadfence();   // release gY stores (per-thread)

    if (t == 0) {
        float H = LN2F * ((m0 + __log2f(l0s) - aa0 / l0s)
                        + (m1 + __log2f(l1s) - aa1 / l1s));
        sred[wid * 8 + g] = H;
    }
    __syncthreads();
    if (tid == 0) {
        float s = 0.f;
#pragma unroll 8
        for (int r = 0; r < 64; r++) s += sred[r];
        g_ent[((size_t)b * NHEAD + h) * NQT2 + qt] = s;
        __threadfence();
        atomicAdd(&g_ff[b * 16 + qt], 1);   // release this token-row tile
    }
}

// ---------------------------------------------------------------------
// fused kernel: QKV tiles | flash | proj (+entropy)
// ---------------------------------------------------------------------
__global__ __launch_bounds__(256, 2) void fused_all(float* __restrict__ out, int out_size)
{
    const int bid = (int)blockIdx.x;
    const int tid = threadIdx.x;

    if (bid < NQKV_B) {
        // ---- QKV gemm role: bm interleaved b0/b1, ascending ----
        const int bn  = (bid % 24) * 128;
        const int bmi = bid / 24;
        const int bm_t = (bmi >> 1) + ((bmi & 1) << 4);   // 0,16,1,17,...
        gemm_tile<1>(gX, gWA, nullptr, C3, CDIM, bm_t * 128, bn);
        __threadfence();
        __syncthreads();
        if (tid == 0) atomicAdd(&g_fq[bm_t], 1);
    } else if (bid < NQKV_B + NFLASH_B) {
        flash_role(bid - NQKV_B);
    } else {
        // ---- proj role: bm interleaved, ascending qt ----
        const int pid = bid - NQKV_B - NFLASH_B;
        const int bn  = (pid & 7) * 128;
        const int pmi = pid >> 3;
        const int bm_t = (pmi >> 1) + ((pmi & 1) << 4);
        if (tid == 0) {
            while (atomicAdd(&g_ff[bm_t], 0) < 16) {}
            __threadfence();
        }
        __syncthreads();
        gemm_tile<0>(gY, gWP, out, CDIM, CDIM, bm_t * 128, bn);

        if (pid == 0) {
            // entropy scalar: needs ALL flash blocks
            if (tid == 0) {
                for (int i = 0; i < 32; i++)
                    while (atomicAdd(&g_ff[i], 0) < 16) {}
                __threadfence();
            }
            __syncthreads();
            __shared__ float red[256];
            float s = 0.f;
            for (int i = tid; i < BATCH * NHEAD * NQT2; i += 256) s += g_ent[i];
            red[tid] = s;
            __syncthreads();
            for (int st = 128; st > 0; st >>= 1) {
                if (tid < st) red[tid] += red[tid + st];
                __syncthreads();
            }
            if (tid == 0) out[out_size - 1] = red[0] / (float)NROWS;
        }
    }
}

// =====================================================================
// launch
// =====================================================================
extern "C" void kernel_launch(void* const* d_in, const int* in_sizes, int n_in,
                              void* d_out, int out_size)
{
    const float* x      = (const float*)d_in[0];
    const float* w_attn = (const float*)d_in[1];
    const float* w_proj = (const float*)d_in[2];
    float* out = (float*)d_out;
    (void)in_sizes; (void)n_in;

    const int FUSED_SMEM = FKV0 + 3 * FSTG;   // 65536 (max of roles)
    cudaFuncSetAttribute(fused_all,
                         cudaFuncAttributeMaxDynamicSharedMemorySize, FUSED_SMEM);

    // 0) prep: fp16 planes + zero flags
    {
        int blocks = (NT4 + 1023) / 1024;
        prep_kernel<<<blocks, 256>>>(x, w_attn, w_proj);
    }
    // 1) fused QKV gemm + flash attention + proj gemm + entropy
    {
        fused_all<<<NQKV_B + NFLASH_B + NPROJ_B, 256, FUSED_SMEM>>>(out, out_size);
    }
}

// round 14
// speedup vs baseline: 1.0524x; 1.0524x over previous
#include <cuda_runtime.h>
#include <cuda_fp16.h>
#include <stdint.h>

// ---------------- problem constants ----------------
#define BATCH  2
#define TQ     2048
#define CDIM   1024
#define NHEAD  16
#define DHEAD  64
#define C3     (3 * CDIM)
#define NQT2   (TQ / 128)
#define NROWS  (BATCH * NHEAD * TQ)
#define QKVN   (BATCH * NHEAD * TQ * DHEAD)
#define LN2F   0.6931471805599453f
#define SC2F   0.1803368801111601f   // 0.125 * log2(e)

#define NQKV_I   768   // 32 row tiles x 24 col tiles
#define NFLASH_I 512
#define NPROJ_I  256
#define NITEMS   (NQKV_I + NFLASH_I + NPROJ_I + 1)   // +1 entropy
#define GRID_P   296   // 2 CTAs x 148 SMs (queue is safe for any SM count)

// ---------------- fp16 planes + flags (device scratch) ----------------
__device__ __align__(16) __half gX[BATCH*TQ*CDIM];
__device__ __align__(16) __half gWA[CDIM*C3];
__device__ __align__(16) __half gWP[CDIM*CDIM];
__device__ __align__(16) __half gQ[QKVN];   // stored PRE-SCALED by SC2F
__device__ __align__(16) __half gK[QKVN];
__device__ __align__(16) __half gV[QKVN];
__device__ __align__(16) __half gY[BATCH*TQ*CDIM];
__device__ float g_ent[BATCH * NHEAD * NQT2];
__device__ int g_fq[32];   // per token-row-tile: # of 24 qkv col tiles done
__device__ int g_ff[32];   // per token-row-tile: # of 16 flash head-blocks done
__device__ int g_wq;       // work-queue counter

// ---------------- helpers ----------------
__device__ __forceinline__ unsigned round2h(float a, float b) {
    __half2 h = __floats2half2_rn(a, b);
    return *reinterpret_cast<unsigned*>(&h);
}
__device__ __forceinline__ float ex2f(float x) {
    float r; asm("ex2.approx.f32 %0, %1;" : "=f"(r) : "f"(x)); return r;
}
__device__ __forceinline__ unsigned ex2h2(unsigned x) {
    unsigned r; asm("ex2.approx.f16x2 %0, %1;" : "=r"(r) : "r"(x)); return r;
}
__device__ __forceinline__ void mma16(float* c, const unsigned* a, unsigned b0, unsigned b1) {
    asm("mma.sync.aligned.m16n8k16.row.col.f32.f16.f16.f32 "
        "{%0,%1,%2,%3},{%4,%5,%6,%7},{%8,%9},{%0,%1,%2,%3};"
        : "+f"(c[0]), "+f"(c[1]), "+f"(c[2]), "+f"(c[3])
        : "r"(a[0]), "r"(a[1]), "r"(a[2]), "r"(a[3]), "r"(b0), "r"(b1));
}
__device__ __forceinline__ void ldsm4(unsigned& r0, unsigned& r1, unsigned& r2, unsigned& r3, uint32_t a) {
    asm volatile("ldmatrix.sync.aligned.m8n8.x4.shared.b16 {%0,%1,%2,%3},[%4];"
        : "=r"(r0), "=r"(r1), "=r"(r2), "=r"(r3) : "r"(a));
}
__device__ __forceinline__ void ldsm4t(unsigned& r0, unsigned& r1, unsigned& r2, unsigned& r3, uint32_t a) {
    asm volatile("ldmatrix.sync.aligned.m8n8.x4.trans.shared.b16 {%0,%1,%2,%3},[%4];"
        : "=r"(r0), "=r"(r1), "=r"(r2), "=r"(r3) : "r"(a));
}
__device__ __forceinline__ void cpa16(uint32_t d, const void* s) {
    asm volatile("cp.async.ca.shared.global [%0],[%1],16;" :: "r"(d), "l"(s));
}
#define CP_COMMIT() asm volatile("cp.async.commit_group;" ::: "memory")
#define CP_WAIT(N)  asm volatile("cp.async.wait_group %0;" :: "n"(N) : "memory")

// =====================================================================
// prep: round inputs to fp16 planes + zero flags/queue
// =====================================================================
#define NX4 (BATCH * TQ * CDIM / 4)
#define NA4 (CDIM * C3 / 4)
#define NP4 (CDIM * CDIM / 4)
#define NT4 (NX4 + NA4 + NP4)
__global__ void prep_kernel(const float* __restrict__ x,
                            const float* __restrict__ wa,
                            const float* __restrict__ wp)
{
    if (blockIdx.x == 0 && threadIdx.x < 65) {
        if (threadIdx.x < 32)      g_fq[threadIdx.x] = 0;
        else if (threadIdx.x < 64) g_ff[threadIdx.x - 32] = 0;
        else                       g_wq = 0;
    }
    int base = blockIdx.x * (blockDim.x * 4) + threadIdx.x;
#pragma unroll
    for (int u = 0; u < 4; u++) {
        int i = base + u * 256;
        if (i >= NT4) return;
        const float* in; __half* out; int j;
        if (i < NX4)            { in = x;  out = gX;  j = i; }
        else if (i < NX4 + NA4) { in = wa; out = gWA; j = i - NX4; }
        else                    { in = wp; out = gWP; j = i - NX4 - NA4; }
        float4 v = ((const float4*)in)[j];
        ((uint2*)out)[j] = make_uint2(round2h(v.x, v.y), round2h(v.z, v.w));
    }
}

// =====================================================================
// shared-memory layouts
// =====================================================================
#define GSTG 16384
#define FKV0 16384
#define FSTG 16384
extern __shared__ char dsm[];

// ---------------------------------------------------------------------
// GEMM tile body (128x128, BK=32, 3-stage cp.async)
// ---------------------------------------------------------------------
__device__ __forceinline__ void gemm_issue(
    uint32_t s0, const __half* A, const __half* B,
    int bm, int bn, int k0, int K, int N, int tid)
{
#pragma unroll
    for (int it = 0; it < 2; it++) {
        int id = tid + it * 256;
        int r = id >> 2, c = id & 3;
        uint32_t d = s0 + r * 64 + ((c ^ ((r >> 1) & 3)) << 4);
        cpa16(d, A + (size_t)(bm + r) * K + k0 + c * 8);
    }
#pragma unroll
    for (int it = 0; it < 2; it++) {
        int id = tid + it * 256;
        int k = id >> 4, c = id & 15;
        uint32_t d = s0 + 8192 + k * 256 + ((c ^ (k & 7)) << 4);
        cpa16(d, B + (size_t)(k0 + k) * N + bn + c * 8);
    }
}

template<int MODE>
__device__ void gemm_tile(const __half* __restrict__ A,
                          const __half* __restrict__ B,
                          float* __restrict__ C,
                          int N, int K, int bm, int bn)
{
    const uint32_t sb = (uint32_t)__cvta_generic_to_shared(dsm);
    const int tid = threadIdx.x, lane = tid & 31, wid = tid >> 5;
    const int g = lane >> 2, t = lane & 3;
    const int m8 = lane >> 3, ri = lane & 7;
    const int wm = wid & 3, wn = wid >> 2;

    float acc[2][8][4];
#pragma unroll
    for (int mt = 0; mt < 2; mt++)
#pragma unroll
        for (int nt = 0; nt < 8; nt++)
#pragma unroll
            for (int i = 0; i < 4; i++) acc[mt][nt][i] = 0.f;

    const int NCH = K / 32;
    gemm_issue(sb,        A, B, bm, bn, 0,  K, N, tid); CP_COMMIT();
    gemm_issue(sb + GSTG, A, B, bm, bn, 32, K, N, tid); CP_COMMIT();

    for (int ch = 0; ch < NCH; ch++) {
        if (ch + 2 < NCH)
            gemm_issue(sb + ((ch + 2) % 3) * GSTG, A, B,
                       bm, bn, (ch + 2) * 32, K, N, tid);
        CP_COMMIT();
        CP_WAIT(2);
        __syncthreads();

        const uint32_t s0 = sb + (ch % 3) * GSTG;
#pragma unroll
        for (int ks = 0; ks < 2; ks++) {
            unsigned ah[2][4];
#pragma unroll
            for (int mt = 0; mt < 2; mt++) {
                int row = wm * 32 + mt * 16 + (m8 & 1) * 8 + ri;
                int c4  = 2 * ks + (m8 >> 1);
                uint32_t a = s0 + row * 64 + ((c4 ^ ((row >> 1) & 3)) << 4);
                ldsm4(ah[mt][0], ah[mt][1], ah[mt][2], ah[mt][3], a);
            }
#pragma unroll
            for (int ntp = 0; ntp < 4; ntp++) {
                int kr = 16 * ks + (m8 & 1) * 8 + ri;
                int cc = wn * 8 + ntp * 2 + (m8 >> 1);
                uint32_t ba = s0 + 8192 + kr * 256 + ((cc ^ (kr & 7)) << 4);
                unsigned bh[4];
                ldsm4t(bh[0], bh[1], bh[2], bh[3], ba);
                mma16(acc[0][ntp * 2 + 0], ah[0], bh[0], bh[1]);
                mma16(acc[1][ntp * 2 + 0], ah[1], bh[0], bh[1]);
                mma16(acc[0][ntp * 2 + 1], ah[0], bh[2], bh[3]);
                mma16(acc[1][ntp * 2 + 1], ah[1], bh[2], bh[3]);
            }
        }
        __syncthreads();
    }

    if (MODE == 0) {
#pragma unroll
        for (int mt = 0; mt < 2; mt++) {
#pragma unroll
            for (int nt = 0; nt < 8; nt++) {
                const int row = bm + wm * 32 + mt * 16 + g;
                const int col = bn + wn * 64 + nt * 8 + 2 * t;
                *(float2*)&C[(size_t)row * N + col] =
                    make_float2(acc[mt][nt][0], acc[mt][nt][1]);
                *(float2*)&C[(size_t)(row + 8) * N + col] =
                    make_float2(acc[mt][nt][2], acc[mt][nt][3]);
            }
        }
    } else {
#pragma unroll
        for (int mt = 0; mt < 2; mt++) {
#pragma unroll
            for (int nt = 0; nt < 8; nt++) {
                const int row = bm + wm * 32 + mt * 16 + g;
                const int col = bn + wn * 64 + nt * 8 + 2 * t;
                const int sec = col >> 10, hh = (col >> 6) & 15, d = col & 63;
                const int bb = row >> 11, tok = row & 2047;
                size_t idx = (((size_t)bb * NHEAD + hh) * TQ + tok) * DHEAD + d;
                __half* p = (sec == 0) ? gQ : ((sec == 1) ? gK : gV);
                const float sc = (sec == 0) ? SC2F : 1.f;
                *(unsigned*)&p[idx] =
                    round2h(acc[mt][nt][0] * sc, acc[mt][nt][1] * sc);
                *(unsigned*)&p[idx + 8 * DHEAD] =
                    round2h(acc[mt][nt][2] * sc, acc[mt][nt][3] * sc);
            }
        }
    }
}

// ---------------------------------------------------------------------
// flash role body
// ---------------------------------------------------------------------
__device__ __forceinline__ void flash_issue_kv(uint32_t s0, size_t base, int j, int tid)
{
#pragma unroll
    for (int it = 0; it < 2; it++) {
        int id = tid + it * 256;
        int r = id >> 3, c = id & 7;
        uint32_t d = s0 + r * 128 + ((c ^ (r & 7)) << 4);
        size_t go = base + (size_t)(j * 64 + r) * DHEAD + c * 8;
        cpa16(d,        gK + go);
        cpa16(d + 8192, gV + go);
    }
}

__device__ void flash_role(int fid)
{
    __shared__ float sred[64];
    const uint32_t sb = (uint32_t)__cvta_generic_to_shared(dsm);
    const int qt = fid >> 5;                  // ascending: earliest-ready first
    const int hb = fid & 31;
    const int h = hb & 15, b = hb >> 4;
    const int tid = threadIdx.x, lane = tid & 31, wid = tid >> 5;
    const int g = lane >> 2, t = lane & 3;
    const int m8 = lane >> 3, ri = lane & 7;
    const size_t base = (size_t)(b * NHEAD + h) * TQ * DHEAD;
    const int nj = 2 * qt + 2;

    // acquire: QKV row tiles b*16 .. b*16+qt
    if (tid == 0) {
        for (int i = 0; i <= qt; i++)
            while (atomicAdd(&g_fq[b * 16 + i], 0) < 24) {}
        __threadfence();
    }
    __syncthreads();

#pragma unroll
    for (int it = 0; it < 4; it++) {
        int id = tid + it * 256;
        int r = id >> 3, c = id & 7;
        uint32_t d = sb + r * 128 + ((c ^ (r & 7)) << 4);
        cpa16(d, gQ + base + (size_t)(qt * 128 + r) * DHEAD + c * 8);
    }
    flash_issue_kv(sb + FKV0, base, 0, tid);
    CP_COMMIT();
    flash_issue_kv(sb + FKV0 + FSTG, base, 1, tid);
    CP_COMMIT();
    CP_WAIT(1);
    __syncthreads();

    unsigned qh[4][4];
#pragma unroll
    for (int ks = 0; ks < 4; ks++) {
        int row = wid * 16 + (m8 & 1) * 8 + ri;
        int c = 2 * ks + (m8 >> 1);
        uint32_t a = sb + row * 128 + ((c ^ (row & 7)) << 4);
        ldsm4(qh[ks][0], qh[ks][1], qh[ks][2], qh[ks][3], a);
    }

    float oc[8][4];
#pragma unroll
    for (int nt = 0; nt < 8; nt++)
#pragma unroll
        for (int i = 0; i < 4; i++) oc[nt][i] = 0.f;

    float m0 = -1e30f, m1 = -1e30f, l0s = 0.f, l1s = 0.f, aa0 = 0.f, aa1 = 0.f;
    const int rowbase = qt * 128 + wid * 16;
    int st2 = 2;

    for (int j = 0; j < nj; j++) {
        CP_WAIT(1);
        __syncthreads();
        if (j + 2 < nj) flash_issue_kv(sb + FKV0 + st2 * FSTG, base, j + 2, tid);
        CP_COMMIT();
        const uint32_t kv = sb + FKV0 + (st2 == 2 ? 0 : st2 + 1) * FSTG;
        st2 = (st2 == 2) ? 0 : st2 + 1;

        const bool active = (rowbase + 16) > (j * 64);
        if (!active) continue;

        float sc[8][4];
#pragma unroll
        for (int nt = 0; nt < 8; nt++)
#pragma unroll
            for (int i = 0; i < 4; i++) sc[nt][i] = 0.f;

#pragma unroll
        for (int ks = 0; ks < 4; ks++) {
#pragma unroll
            for (int ntp = 0; ntp < 4; ntp++) {
                int kr = ntp * 16 + (m8 & 1) * 8 + ri;
                int c = 2 * ks + (m8 >> 1);
                uint32_t ka = kv + kr * 128 + ((c ^ (kr & 7)) << 4);
                unsigned kh[4];
                ldsm4(kh[0], kh[1], kh[2], kh[3], ka);
                mma16(sc[2 * ntp],     qh[ks], kh[0], kh[2]);
                mma16(sc[2 * ntp + 1], qh[ks], kh[1], kh[3]);
            }
        }

        if ((j * 64 + 63) > rowbase) {
#pragma unroll
            for (int nt = 0; nt < 8; nt++) {
#pragma unroll
                for (int cc = 0; cc < 4; cc++) {
                    int col = j * 64 + nt * 8 + 2 * t + (cc & 1);
                    int row = rowbase + g + ((cc >> 1) << 3);
                    if (col > row) sc[nt][cc] = -1e30f;
                }
            }
        }

        float mt0 = -1e30f, mt1 = -1e30f;
#pragma unroll
        for (int nt = 0; nt < 8; nt++) {
            mt0 = fmaxf(mt0, fmaxf(sc[nt][0], sc[nt][1]));
            mt1 = fmaxf(mt1, fmaxf(sc[nt][2], sc[nt][3]));
        }
        mt0 = fmaxf(mt0, __shfl_xor_sync(0xffffffffu, mt0, 1));
        mt0 = fmaxf(mt0, __shfl_xor_sync(0xffffffffu, mt0, 2));
        mt1 = fmaxf(mt1, __shfl_xor_sync(0xffffffffu, mt1, 1));
        mt1 = fmaxf(mt1, __shfl_xor_sync(0xffffffffu, mt1, 2));

        const float mn0 = fmaxf(m0, mt0), mn1 = fmaxf(m1, mt1);
        const float ex0 = ex2f(m0 - mn0), ex1 = ex2f(m1 - mn1);
        const __half2 mn0h = __float2half2_rn(mn0);
        const __half2 mn1h = __float2half2_rn(mn1);

        unsigned ph0[8], ph1[8];
        float ls0 = 0.f, ls1 = 0.f, as0 = 0.f, as1 = 0.f;
#pragma unroll
        for (int nt = 0; nt < 8; nt++) {
            __half2 h0 = __floats2half2_rn(sc[nt][0], sc[nt][1]);
            __half2 h1 = __floats2half2_rn(sc[nt][2], sc[nt][3]);
            __half2 d0 = __hsub2(h0, mn0h);
            __half2 d1 = __hsub2(h1, mn1h);
            unsigned p0 = ex2h2(*reinterpret_cast<unsigned*>(&d0));
            unsigned p1 = ex2h2(*reinterpret_cast<unsigned*>(&d1));
            ph0[nt] = p0; ph1[nt] = p1;
            float2 f0 = __half22float2(*reinterpret_cast<__half2*>(&p0));
            float2 f1 = __half22float2(*reinterpret_cast<__half2*>(&p1));
            ls0 += f0.x + f0.y;  ls1 += f1.x + f1.y;
            as0 += f0.x * sc[nt][0] + f0.y * sc[nt][1];
            as1 += f1.x * sc[nt][2] + f1.y * sc[nt][3];
        }
        ls0 += __shfl_xor_sync(0xffffffffu, ls0, 1);
        ls0 += __shfl_xor_sync(0xffffffffu, ls0, 2);
        ls1 += __shfl_xor_sync(0xffffffffu, ls1, 1);
        ls1 += __shfl_xor_sync(0xffffffffu, ls1, 2);
        as0 += __shfl_xor_sync(0xffffffffu, as0, 1);
        as0 += __shfl_xor_sync(0xffffffffu, as0, 2);
        as1 += __shfl_xor_sync(0xffffffffu, as1, 1);
        as1 += __shfl_xor_sync(0xffffffffu, as1, 2);

        l0s = l0s * ex0 + ls0;  aa0 = aa0 * ex0 + as0;  m0 = mn0;
        l1s = l1s * ex1 + ls1;  aa1 = aa1 * ex1 + as1;  m1 = mn1;

#pragma unroll
        for (int nt = 0; nt < 8; nt++) {
            oc[nt][0] *= ex0; oc[nt][1] *= ex0;
            oc[nt][2] *= ex1; oc[nt][3] *= ex1;
        }

#pragma unroll
        for (int ks = 0; ks < 4; ks++) {
            unsigned aH[4] = {ph0[2*ks], ph1[2*ks], ph0[2*ks+1], ph1[2*ks+1]};
#pragma unroll
            for (int ntp = 0; ntp < 4; ntp++) {
                int vr = 16 * ks + (m8 & 1) * 8 + ri;
                int c = ntp * 2 + (m8 >> 1);
                uint32_t va = kv + 8192 + vr * 128 + ((c ^ (vr & 7)) << 4);
                unsigned vh[4];
                ldsm4t(vh[0], vh[1], vh[2], vh[3], va);
                mma16(oc[2 * ntp],     aH, vh[0], vh[1]);
                mma16(oc[2 * ntp + 1], aH, vh[2], vh[3]);
            }
        }
    }

    const float inv0 = 1.f / l0s, inv1 = 1.f / l1s;
    const int trow = rowbase + g;
#pragma unroll
    for (int nt = 0; nt < 8; nt++) {
        const int col = h * DHEAD + nt * 8 + 2 * t;
        size_t idx = ((size_t)b * TQ + trow) * CDIM + col;
        *(unsigned*)&gY[idx] = round2h(oc[nt][0] * inv0, oc[nt][1] * inv0);
        *(unsigned*)&gY[idx + 8 * CDIM] = round2h(oc[nt][2] * inv1, oc[nt][3] * inv1);
    }
    __threadfence();

    if (t == 0) {
        float H = LN2F * ((m0 + __log2f(l0s) - aa0 / l0s)
                        + (m1 + __log2f(l1s) - aa1 / l1s));
        sred[wid * 8 + g] = H;
    }
    __syncthreads();
    if (tid == 0) {
        float s = 0.f;
#pragma unroll 8
        for (int r = 0; r < 64; r++) s += sred[r];
        g_ent[((size_t)b * NHEAD + h) * NQT2 + qt] = s;
        __threadfence();
        atomicAdd(&g_ff[b * 16 + qt], 1);
    }
}

// ---------------------------------------------------------------------
// persistent kernel: each block drains the ordered work queue
// ---------------------------------------------------------------------
__global__ __launch_bounds__(256, 2) void persist_all(float* __restrict__ out, int out_size)
{
    __shared__ int s_item;
    const int tid = threadIdx.x;

    for (;;) {
        CP_WAIT(0);          // clean cp.async state between items
        __syncthreads();     // smem reuse + s_item protection
        if (tid == 0) s_item = atomicAdd(&g_wq, 1);
        __syncthreads();
        const int item = s_item;
        if (item >= NITEMS) break;

        if (item < NQKV_I) {
            // QKV tile: row-tile-major (all 24 col tiles of a row adjacent),
            // rows interleaved b0/b1 so both batches' low qt land first.
            const int bmi = item / 24;
            const int bn  = (item % 24) * 128;
            const int bm_t = (bmi >> 1) + ((bmi & 1) << 4);
            gemm_tile<1>(gX, gWA, nullptr, C3, CDIM, bm_t * 128, bn);
            __threadfence();
            __syncthreads();
            if (tid == 0) atomicAdd(&g_fq[bm_t], 1);
        } else if (item < NQKV_I + NFLASH_I) {
            flash_role(item - NQKV_I);
        } else if (item < NQKV_I + NFLASH_I + NPROJ_I) {
            const int pid = item - NQKV_I - NFLASH_I;
            const int bn  = (pid & 7) * 128;
            const int pmi = pid >> 3;
            const int bm_t = (pmi >> 1) + ((pmi & 1) << 4);
            if (tid == 0) {
                while (atomicAdd(&g_ff[bm_t], 0) < 16) {}
                __threadfence();
            }
            __syncthreads();
            gemm_tile<0>(gY, gWP, out, CDIM, CDIM, bm_t * 128, bn);
        } else {
            // entropy scalar (last item)
            if (tid == 0) {
                for (int i = 0; i < 32; i++)
                    while (atomicAdd(&g_ff[i], 0) < 16) {}
                __threadfence();
            }
            __syncthreads();
            float* red = (float*)dsm;
            float s = 0.f;
            for (int i = tid; i < BATCH * NHEAD * NQT2; i += 256) s += g_ent[i];
            red[tid] = s;
            __syncthreads();
            for (int st = 128; st > 0; st >>= 1) {
                if (tid < st) red[tid] += red[tid + st];
                __syncthreads();
            }
            if (tid == 0) out[out_size - 1] = red[0] / (float)NROWS;
        }
    }
}

// =====================================================================
// launch
// =====================================================================
extern "C" void kernel_launch(void* const* d_in, const int* in_sizes, int n_in,
                              void* d_out, int out_size)
{
    const float* x      = (const float*)d_in[0];
    const float* w_attn = (const float*)d_in[1];
    const float* w_proj = (const float*)d_in[2];
    float* out = (float*)d_out;
    (void)in_sizes; (void)n_in;

    const int SMEM = FKV0 + 3 * FSTG;   // 65536 (max over roles)
    cudaFuncSetAttribute(persist_all,
                         cudaFuncAttributeMaxDynamicSharedMemorySize, SMEM);

    // 0) prep: fp16 planes + zero flags/queue
    {
        int blocks = (NT4 + 1023) / 1024;
        prep_kernel<<<blocks, 256>>>(x, w_attn, w_proj);
    }
    // 1) persistent fused pipeline
    {
        persist_all<<<GRID_P, 256, SMEM>>>(out, out_size);
    }
}

// round 15
// speedup vs baseline: 1.1206x; 1.0648x over previous
#include <cuda_runtime.h>
#include <cuda_fp16.h>
#include <stdint.h>

// ---------------- problem constants ----------------
#define BATCH  2
#define TQ     2048
#define CDIM   1024
#define NHEAD  16
#define DHEAD  64
#define C3     (3 * CDIM)
#define NQT2   (TQ / 128)
#define NROWS  (BATCH * NHEAD * TQ)
#define QKVN   (BATCH * NHEAD * TQ * DHEAD)
#define LN2F   0.6931471805599453f
#define SC2F   0.1803368801111601f   // 0.125 * log2(e)

// ---------------- fp16 planes (device scratch) ----------------
__device__ __align__(16) __half gX[BATCH*TQ*CDIM];
__device__ __align__(16) __half gWA[CDIM*C3];
__device__ __align__(16) __half gWP[CDIM*CDIM];
__device__ __align__(16) __half gQ[QKVN];   // stored PRE-SCALED by SC2F
__device__ __align__(16) __half gK[QKVN];
__device__ __align__(16) __half gV[QKVN];
__device__ __align__(16) __half gY[BATCH*TQ*CDIM];
__device__ float g_ent[BATCH * NHEAD * NQT2];

// ---------------- helpers ----------------
__device__ __forceinline__ unsigned round2h(float a, float b) {
    __half2 h = __floats2half2_rn(a, b);
    return *reinterpret_cast<unsigned*>(&h);
}
__device__ __forceinline__ float ex2f(float x) {
    float r; asm("ex2.approx.f32 %0, %1;" : "=f"(r) : "f"(x)); return r;
}
__device__ __forceinline__ unsigned ex2h2(unsigned x) {
    unsigned r; asm("ex2.approx.f16x2 %0, %1;" : "=r"(r) : "r"(x)); return r;
}
__device__ __forceinline__ void mma16(float* c, const unsigned* a, unsigned b0, unsigned b1) {
    asm("mma.sync.aligned.m16n8k16.row.col.f32.f16.f16.f32 "
        "{%0,%1,%2,%3},{%4,%5,%6,%7},{%8,%9},{%0,%1,%2,%3};"
        : "+f"(c[0]), "+f"(c[1]), "+f"(c[2]), "+f"(c[3])
        : "r"(a[0]), "r"(a[1]), "r"(a[2]), "r"(a[3]), "r"(b0), "r"(b1));
}
__device__ __forceinline__ void ldsm4(unsigned& r0, unsigned& r1, unsigned& r2, unsigned& r3, uint32_t a) {
    asm volatile("ldmatrix.sync.aligned.m8n8.x4.shared.b16 {%0,%1,%2,%3},[%4];"
        : "=r"(r0), "=r"(r1), "=r"(r2), "=r"(r3) : "r"(a));
}
__device__ __forceinline__ void ldsm4t(unsigned& r0, unsigned& r1, unsigned& r2, unsigned& r3, uint32_t a) {
    asm volatile("ldmatrix.sync.aligned.m8n8.x4.trans.shared.b16 {%0,%1,%2,%3},[%4];"
        : "=r"(r0), "=r"(r1), "=r"(r2), "=r"(r3) : "r"(a));
}
__device__ __forceinline__ void cpa16(uint32_t d, const void* s) {
    asm volatile("cp.async.ca.shared.global [%0],[%1],16;" :: "r"(d), "l"(s));
}
#define CP_COMMIT() asm volatile("cp.async.commit_group;" ::: "memory")
#define CP_WAIT(N)  asm volatile("cp.async.wait_group %0;" :: "n"(N) : "memory")

// =====================================================================
// fused prep: 512 threads x 8 float4 per thread
// =====================================================================
#define NX4 (BATCH * TQ * CDIM / 4)
#define NA4 (CDIM * C3 / 4)
#define NP4 (CDIM * CDIM / 4)
#define NT4 (NX4 + NA4 + NP4)
__global__ void prep_kernel(const float* __restrict__ x,
                            const float* __restrict__ wa,
                            const float* __restrict__ wp)
{
    int base = blockIdx.x * (512 * 8) + threadIdx.x;
#pragma unroll
    for (int u = 0; u < 8; u++) {
        int i = base + u * 512;
        if (i >= NT4) return;
        const float* in; __half* out; int j;
        if (i < NX4)            { in = x;  out = gX;  j = i; }
        else if (i < NX4 + NA4) { in = wa; out = gWA; j = i - NX4; }
        else                    { in = wp; out = gWP; j = i - NX4 - NA4; }
        float4 v = ((const float4*)in)[j];
        ((uint2*)out)[j] = make_uint2(round2h(v.x, v.y), round2h(v.z, v.w));
    }
}

// =====================================================================
// GEMM (fp16): C = A @ B. 128x128 tile, BK=32, 256 thr, 3-stage cp.async,
// ONE barrier per chunk (flash-style pipeline, proven in R11).
// mode 0: fp32 C (+ block(0,0) entropy); mode 1: qkv scatter (Q pre-scaled).
// =====================================================================
#define GSTG 16384
extern __shared__ char dsm[];

__device__ __forceinline__ void gemm_issue(
    uint32_t s0, const __half* A, const __half* B,
    int bm, int bn, int k0, int K, int N, int tid)
{
#pragma unroll
    for (int it = 0; it < 2; it++) {
        int id = tid + it * 256;
        int r = id >> 2, c = id & 3;
        uint32_t d = s0 + r * 64 + ((c ^ ((r >> 1) & 3)) << 4);
        cpa16(d, A + (size_t)(bm + r) * K + k0 + c * 8);
    }
#pragma unroll
    for (int it = 0; it < 2; it++) {
        int id = tid + it * 256;
        int k = id >> 4, c = id & 15;
        uint32_t d = s0 + 8192 + k * 256 + ((c ^ (k & 7)) << 4);
        cpa16(d, B + (size_t)(k0 + k) * N + bn + c * 8);
    }
}

__global__ __launch_bounds__(256, 2) void gemm_h1(
    const __half* __restrict__ A, const __half* __restrict__ B,
    float* __restrict__ C, int M, int N, int K, int mode, int out_size)
{
    const uint32_t sb = (uint32_t)__cvta_generic_to_shared(dsm);
    const int tid = threadIdx.x, lane = tid & 31, wid = tid >> 5;
    const int g = lane >> 2, t = lane & 3;
    const int m8 = lane >> 3, ri = lane & 7;
    const int wm = wid & 3, wn = wid >> 2;
    const int bm = blockIdx.y * 128, bn = blockIdx.x * 128;

    if (mode == 0 && blockIdx.x == 0 && blockIdx.y == 0) {
        __shared__ float red[256];
        float s = 0.f;
        for (int i = tid; i < BATCH * NHEAD * NQT2; i += 256) s += g_ent[i];
        red[tid] = s;
        __syncthreads();
        for (int st = 128; st > 0; st >>= 1) {
            if (tid < st) red[tid] += red[tid + st];
            __syncthreads();
        }
        if (tid == 0) C[out_size - 1] = red[0] / (float)NROWS;
    }

    float acc[2][8][4];
#pragma unroll
    for (int mt = 0; mt < 2; mt++)
#pragma unroll
        for (int nt = 0; nt < 8; nt++)
#pragma unroll
            for (int i = 0; i < 4; i++) acc[mt][nt][i] = 0.f;

    const int NCH = K / 32;
    gemm_issue(sb,        A, B, bm, bn, 0,  K, N, tid); CP_COMMIT();
    gemm_issue(sb + GSTG, A, B, bm, bn, 32, K, N, tid); CP_COMMIT();

    for (int ch = 0; ch < NCH; ch++) {
        CP_WAIT(1);          // group ch complete (per-thread)
        __syncthreads();     // block-wide; also frees stage (ch-1)%3
        if (ch + 2 < NCH)
            gemm_issue(sb + ((ch + 2) % 3) * GSTG, A, B,
                       bm, bn, (ch + 2) * 32, K, N, tid);
        CP_COMMIT();

        const uint32_t s0 = sb + (ch % 3) * GSTG;
#pragma unroll
        for (int ks = 0; ks < 2; ks++) {
            unsigned ah[2][4];
#pragma unroll
            for (int mt = 0; mt < 2; mt++) {
                int row = wm * 32 + mt * 16 + (m8 & 1) * 8 + ri;
                int c4  = 2 * ks + (m8 >> 1);
                uint32_t a = s0 + row * 64 + ((c4 ^ ((row >> 1) & 3)) << 4);
                ldsm4(ah[mt][0], ah[mt][1], ah[mt][2], ah[mt][3], a);
            }
#pragma unroll
            for (int ntp = 0; ntp < 4; ntp++) {
                int kr = 16 * ks + (m8 & 1) * 8 + ri;
                int cc = wn * 8 + ntp * 2 + (m8 >> 1);
                uint32_t ba = s0 + 8192 + kr * 256 + ((cc ^ (kr & 7)) << 4);
                unsigned bh[4];
                ldsm4t(bh[0], bh[1], bh[2], bh[3], ba);
                mma16(acc[0][ntp * 2 + 0], ah[0], bh[0], bh[1]);
                mma16(acc[1][ntp * 2 + 0], ah[1], bh[0], bh[1]);
                mma16(acc[0][ntp * 2 + 1], ah[0], bh[2], bh[3]);
                mma16(acc[1][ntp * 2 + 1], ah[1], bh[2], bh[3]);
            }
        }
    }

    // ---- epilogue ----
    if (mode == 0) {
#pragma unroll
        for (int mt = 0; mt < 2; mt++) {
#pragma unroll
            for (int nt = 0; nt < 8; nt++) {
                const int row = bm + wm * 32 + mt * 16 + g;
                const int col = bn + wn * 64 + nt * 8 + 2 * t;
                *(float2*)&C[(size_t)row * N + col] =
                    make_float2(acc[mt][nt][0], acc[mt][nt][1]);
                *(float2*)&C[(size_t)(row + 8) * N + col] =
                    make_float2(acc[mt][nt][2], acc[mt][nt][3]);
            }
        }
    } else {
#pragma unroll
        for (int mt = 0; mt < 2; mt++) {
#pragma unroll
            for (int nt = 0; nt < 8; nt++) {
                const int row = bm + wm * 32 + mt * 16 + g;
                const int col = bn + wn * 64 + nt * 8 + 2 * t;
                const int sec = col >> 10, hh = (col >> 6) & 15, d = col & 63;
                const int bb = row >> 11, tok = row & 2047;
                size_t idx = (((size_t)bb * NHEAD + hh) * TQ + tok) * DHEAD + d;
                __half* p = (sec == 0) ? gQ : ((sec == 1) ? gK : gV);
                const float sc = (sec == 0) ? SC2F : 1.f;   // pre-scale Q
                *(unsigned*)&p[idx] =
                    round2h(acc[mt][nt][0] * sc, acc[mt][nt][1] * sc);
                *(unsigned*)&p[idx + 8 * DHEAD] =
                    round2h(acc[mt][nt][2] * sc, acc[mt][nt][3] * sc);
            }
        }
    }
}

// =====================================================================
// Flash attention: fp16, base-2 f16x2 softmax, 3-stage KV ring,
// one barrier/tile, inactive-warp skip + diag-only mask. 64KB smem, occ 2.
// (identical to R12)
// =====================================================================
#define FKV0 16384
#define FSTG 16384

__device__ __forceinline__ void flash_issue_kv(uint32_t s0, size_t base, int j, int tid)
{
#pragma unroll
    for (int it = 0; it < 2; it++) {
        int id = tid + it * 256;
        int r = id >> 3, c = id & 7;
        uint32_t d = s0 + r * 128 + ((c ^ (r & 7)) << 4);
        size_t go = base + (size_t)(j * 64 + r) * DHEAD + c * 8;
        cpa16(d,        gK + go);
        cpa16(d + 8192, gV + go);
    }
}

__global__ __launch_bounds__(256, 2) void flash_h1()
{
    __shared__ float sred[64];
    const uint32_t sb = (uint32_t)__cvta_generic_to_shared(dsm);
    const int bid = (int)blockIdx.x;
    const int qt = NQT2 - 1 - (bid >> 5);     // global longest-first
    const int hb = bid & 31;
    const int h = hb & 15, b = hb >> 4;
    const int tid = threadIdx.x, lane = tid & 31, wid = tid >> 5;
    const int g = lane >> 2, t = lane & 3;
    const int m8 = lane >> 3, ri = lane & 7;
    const size_t base = (size_t)(b * NHEAD + h) * TQ * DHEAD;
    const int nj = 2 * qt + 2;

    // ---- prologue: Q + KV0 (group A), KV1 (group B) ----
#pragma unroll
    for (int it = 0; it < 4; it++) {
        int id = tid + it * 256;
        int r = id >> 3, c = id & 7;
        uint32_t d = sb + r * 128 + ((c ^ (r & 7)) << 4);
        cpa16(d, gQ + base + (size_t)(qt * 128 + r) * DHEAD + c * 8);
    }
    flash_issue_kv(sb + FKV0, base, 0, tid);
    CP_COMMIT();
    flash_issue_kv(sb + FKV0 + FSTG, base, 1, tid);
    CP_COMMIT();
    CP_WAIT(1);
    __syncthreads();

    // ---- hoist Q fragments ----
    unsigned qh[4][4];
#pragma unroll
    for (int ks = 0; ks < 4; ks++) {
        int row = wid * 16 + (m8 & 1) * 8 + ri;
        int c = 2 * ks + (m8 >> 1);
        uint32_t a = sb + row * 128 + ((c ^ (row & 7)) << 4);
        ldsm4(qh[ks][0], qh[ks][1], qh[ks][2], qh[ks][3], a);
    }

    float oc[8][4];
#pragma unroll
    for (int nt = 0; nt < 8; nt++)
#pragma unroll
        for (int i = 0; i < 4; i++) oc[nt][i] = 0.f;

    float m0 = -1e30f, m1 = -1e30f, l0s = 0.f, l1s = 0.f, aa0 = 0.f, aa1 = 0.f;
    const int rowbase = qt * 128 + wid * 16;
    int st2 = 2;

    for (int j = 0; j < nj; j++) {
        CP_WAIT(1);
        __syncthreads();
        if (j + 2 < nj) flash_issue_kv(sb + FKV0 + st2 * FSTG, base, j + 2, tid);
        CP_COMMIT();
        const uint32_t kv = sb + FKV0 + (st2 == 2 ? 0 : st2 + 1) * FSTG;
        st2 = (st2 == 2) ? 0 : st2 + 1;

        const bool active = (rowbase + 16) > (j * 64);
        if (!active) continue;

        // ---- S = Q K^T ----
        float sc[8][4];
#pragma unroll
        for (int nt = 0; nt < 8; nt++)
#pragma unroll
            for (int i = 0; i < 4; i++) sc[nt][i] = 0.f;

#pragma unroll
        for (int ks = 0; ks < 4; ks++) {
#pragma unroll
            for (int ntp = 0; ntp < 4; ntp++) {
                int kr = ntp * 16 + (m8 & 1) * 8 + ri;
                int c = 2 * ks + (m8 >> 1);
                uint32_t ka = kv + kr * 128 + ((c ^ (kr & 7)) << 4);
                unsigned kh[4];
                ldsm4(kh[0], kh[1], kh[2], kh[3], ka);
                mma16(sc[2 * ntp],     qh[ks], kh[0], kh[2]);
                mma16(sc[2 * ntp + 1], qh[ks], kh[1], kh[3]);
            }
        }

        // ---- causal mask: diagonal tiles only ----
        if ((j * 64 + 63) > rowbase) {
#pragma unroll
            for (int nt = 0; nt < 8; nt++) {
#pragma unroll
                for (int cc = 0; cc < 4; cc++) {
                    int col = j * 64 + nt * 8 + 2 * t + (cc & 1);
                    int row = rowbase + g + ((cc >> 1) << 3);
                    if (col > row) sc[nt][cc] = -1e30f;
                }
            }
        }

        // ---- online softmax (base-2, f16x2 exp) + entropy ----
        float mt0 = -1e30f, mt1 = -1e30f;
#pragma unroll
        for (int nt = 0; nt < 8; nt++) {
            mt0 = fmaxf(mt0, fmaxf(sc[nt][0], sc[nt][1]));
            mt1 = fmaxf(mt1, fmaxf(sc[nt][2], sc[nt][3]));
        }
        mt0 = fmaxf(mt0, __shfl_xor_sync(0xffffffffu, mt0, 1));
        mt0 = fmaxf(mt0, __shfl_xor_sync(0xffffffffu, mt0, 2));
        mt1 = fmaxf(mt1, __shfl_xor_sync(0xffffffffu, mt1, 1));
        mt1 = fmaxf(mt1, __shfl_xor_sync(0xffffffffu, mt1, 2));

        const float mn0 = fmaxf(m0, mt0), mn1 = fmaxf(m1, mt1);
        const float ex0 = ex2f(m0 - mn0), ex1 = ex2f(m1 - mn1);
        const __half2 mn0h = __float2half2_rn(mn0);
        const __half2 mn1h = __float2half2_rn(mn1);

        unsigned ph0[8], ph1[8];
        float ls0 = 0.f, ls1 = 0.f, as0 = 0.f, as1 = 0.f;
#pragma unroll
        for (int nt = 0; nt < 8; nt++) {
            __half2 h0 = __floats2half2_rn(sc[nt][0], sc[nt][1]);
            __half2 h1 = __floats2half2_rn(sc[nt][2], sc[nt][3]);
            __half2 d0 = __hsub2(h0, mn0h);
            __half2 d1 = __hsub2(h1, mn1h);
            unsigned p0 = ex2h2(*reinterpret_cast<unsigned*>(&d0));
            unsigned p1 = ex2h2(*reinterpret_cast<unsigned*>(&d1));
            ph0[nt] = p0; ph1[nt] = p1;
            float2 f0 = __half22float2(*reinterpret_cast<__half2*>(&p0));
            float2 f1 = __half22float2(*reinterpret_cast<__half2*>(&p1));
            ls0 += f0.x + f0.y;  ls1 += f1.x + f1.y;
            as0 += f0.x * sc[nt][0] + f0.y * sc[nt][1];
            as1 += f1.x * sc[nt][2] + f1.y * sc[nt][3];
        }
        ls0 += __shfl_xor_sync(0xffffffffu, ls0, 1);
        ls0 += __shfl_xor_sync(0xffffffffu, ls0, 2);
        ls1 += __shfl_xor_sync(0xffffffffu, ls1, 1);
        ls1 += __shfl_xor_sync(0xffffffffu, ls1, 2);
        as0 += __shfl_xor_sync(0xffffffffu, as0, 1);
        as0 += __shfl_xor_sync(0xffffffffu, as0, 2);
        as1 += __shfl_xor_sync(0xffffffffu, as1, 1);
        as1 += __shfl_xor_sync(0xffffffffu, as1, 2);

        l0s = l0s * ex0 + ls0;  aa0 = aa0 * ex0 + as0;  m0 = mn0;
        l1s = l1s * ex1 + ls1;  aa1 = aa1 * ex1 + as1;  m1 = mn1;

#pragma unroll
        for (int nt = 0; nt < 8; nt++) {
            oc[nt][0] *= ex0; oc[nt][1] *= ex0;
            oc[nt][2] *= ex1; oc[nt][3] *= ex1;
        }

        // ---- O += P @ V ----
#pragma unroll
        for (int ks = 0; ks < 4; ks++) {
            unsigned aH[4] = {ph0[2*ks], ph1[2*ks], ph0[2*ks+1], ph1[2*ks+1]};
#pragma unroll
            for (int ntp = 0; ntp < 4; ntp++) {
                int vr = 16 * ks + (m8 & 1) * 8 + ri;
                int c = ntp * 2 + (m8 >> 1);
                uint32_t va = kv + 8192 + vr * 128 + ((c ^ (vr & 7)) << 4);
                unsigned vh[4];
                ldsm4t(vh[0], vh[1], vh[2], vh[3], va);
                mma16(oc[2 * ntp],     aH, vh[0], vh[1]);
                mma16(oc[2 * ntp + 1], aH, vh[2], vh[3]);
            }
        }
    }

    // ---- epilogue: write yatt fp16 ----
    const float inv0 = 1.f / l0s, inv1 = 1.f / l1s;
    const int trow = rowbase + g;
#pragma unroll
    for (int nt = 0; nt < 8; nt++) {
        const int col = h * DHEAD + nt * 8 + 2 * t;
        size_t idx = ((size_t)b * TQ + trow) * CDIM + col;
        *(unsigned*)&gY[idx] = round2h(oc[nt][0] * inv0, oc[nt][1] * inv0);
        *(unsigned*)&gY[idx + 8 * CDIM] = round2h(oc[nt][2] * inv1, oc[nt][3] * inv1);
    }

    // ---- entropy partial ----
    if (t == 0) {
        float H = LN2F * ((m0 + __log2f(l0s) - aa0 / l0s)
                        + (m1 + __log2f(l1s) - aa1 / l1s));
        sred[wid * 8 + g] = H;
    }
    __syncthreads();
    if (tid == 0) {
        float s = 0.f;
#pragma unroll 8
        for (int r = 0; r < 64; r++) s += sred[r];
        g_ent[((size_t)b * NHEAD + h) * NQT2 + qt] = s;
    }
}

// =====================================================================
// launch (3-kernel structure, proven best)
// =====================================================================
extern "C" void kernel_launch(void* const* d_in, const int* in_sizes, int n_in,
                              void* d_out, int out_size)
{
    const float* x      = (const float*)d_in[0];
    const float* w_attn = (const float*)d_in[1];
    const float* w_proj = (const float*)d_in[2];
    float* out = (float*)d_out;
    (void)in_sizes; (void)n_in;

    __half *xp, *wa, *wp, *yp;
    cudaGetSymbolAddress((void**)&xp, gX);
    cudaGetSymbolAddress((void**)&wa, gWA);
    cudaGetSymbolAddress((void**)&wp, gWP);
    cudaGetSymbolAddress((void**)&yp, gY);

    const int GEMM_SMEM  = 3 * GSTG;           // 49152
    const int FLASH_SMEM = FKV0 + 3 * FSTG;    // 65536
    cudaFuncSetAttribute(gemm_h1,
                         cudaFuncAttributeMaxDynamicSharedMemorySize, GEMM_SMEM);
    cudaFuncSetAttribute(flash_h1,
                         cudaFuncAttributeMaxDynamicSharedMemorySize, FLASH_SMEM);

    // 0) fused prep (512 thr x 8 float4)
    {
        int blocks = (NT4 + 4095) / 4096;
        prep_kernel<<<blocks, 512>>>(x, w_attn, w_proj);
    }
    // 1) qkv = x @ w_attn -> Q (pre-scaled), K, V fp16
    {
        dim3 grid(C3 / 128, (BATCH * TQ) / 128);
        gemm_h1<<<grid, 256, GEMM_SMEM>>>(xp, wa, nullptr,
                                          BATCH * TQ, C3, CDIM, 1, out_size);
    }
    // 2) flash attention (1D longest-first grid) -> gY + entropy partials
    {
        flash_h1<<<NQT2 * NHEAD * BATCH, 256, FLASH_SMEM>>>();
    }
    // 3) y = yatt @ w_proj -> d_out (block(0,0) also writes entropy)
    {
        dim3 grid(CDIM / 128, (BATCH * TQ) / 128);
        gemm_h1<<<grid, 256, GEMM_SMEM>>>(yp, wp, out,
                                          BATCH * TQ, CDIM, CDIM, 0, out_size);
    }
}